// round 13
// baseline (speedup 1.0000x reference)
#include <cuda_runtime.h>
#include <cstdint>

// FastLearnableEMA — fused kernel with cp.async double-buffered x pipeline.
//   a    = clip(sigmoid(logit_alpha), 1e-4, 1-1e-4)             [C]
//   u[t] = x[t]*w[t],  w[0]=1, w[t>0]=(1-a)*a^t
//   y[t] = cumsum_t(u) * min(a^-t, 1e8)     (== cumsum / max(a^t, 1e-8))
//
// Block = (batch b, 32-channel tile, full T). 16 tiles of 128 t; warp w owns
// a 16-t chunk (one channel per lane) scanned from smem. While tile t is
// computed, tile t+2 streams into the same smem buffer slot via cp.async —
// loads never drain during the compute/barrier phase (the round-12 finding:
// DRAM% was capped by load duty cycle, not occupancy/waves).
// x read once (cp.async.cg, L1-bypass), y written once: 256 MB HBM traffic.

#define T_LEN   2048
#define C_LEN   512
#define CT      32                 // channels per block
#define WARPS   8
#define LT      16                 // t per thread per tile
#define TILE_T  (WARPS * LT)       // 128
#define NTILES  (T_LEN / TILE_T)   // 16
#define TILE_F4 (TILE_T * CT / 4)  // 1024 float4 per tile buffer
#define CLAMP_LO 1e-4f
#define CLAMP_HI (1.0f - 1e-4f)
#define INV_EPS  1e8f              // 1/eps

__device__ __forceinline__ void cp_async16(uint32_t saddr, const void* gptr) {
    asm volatile("cp.async.cg.shared.global [%0], [%1], 16;"
                 :: "r"(saddr), "l"(gptr));
}
#define CP_COMMIT() asm volatile("cp.async.commit_group;" ::: "memory")
#define CP_WAIT1()  asm volatile("cp.async.wait_group 1;"  ::: "memory")

__global__ void __launch_bounds__(256, 4) ema_fused(
    const float* __restrict__ x,
    const float* __restrict__ logit_alpha,
    float* __restrict__ y)
{
    const int tid  = threadIdx.x;
    const int warp = tid >> 5;
    const int lane = tid & 31;
    const int b    = blockIdx.x >> 4;                 // C/CT = 16 ctiles per b
    const int c    = ((blockIdx.x & 15) * CT) + lane;

    __shared__ float sx[2][TILE_T * CT];              // 2 x 16 KB x staging
    __shared__ float sm_part[WARPS][CT];
    __shared__ float sm_base[2][CT];

    // per-channel constants
    float la  = logit_alpha[c];
    float a   = 1.0f / (1.0f + expf(-la));
    a = fminf(fmaxf(a, CLAMP_LO), CLAMP_HI);
    const float oma   = 1.0f - a;
    const float inv_a = 1.0f / a;
    const float lg2a  = log2f(a);

    // a^TILE_T, a^-TILE_T (tile stride 128 = 2^7) by repeated squaring
    float aT = a;
    #pragma unroll
    for (int i = 0; i < 7; i++) aT *= aT;             // a^128 (underflow->0 ok)
    float iaT = inv_a;
    #pragma unroll
    for (int i = 0; i < 7; i++) iaT *= iaT;           // a^-128 (inf ok, clamped)

    // chunk-start powers at t = warp*LT (exact 1.0 for warp 0)
    const float t0w   = (float)(warp * LT);
    float ap     = (warp == 0) ? 1.0f : exp2f(t0w * lg2a);
    float inv_ap = (warp == 0) ? 1.0f : exp2f(-t0w * lg2a);

    const size_t row  = (size_t)b * T_LEN * C_LEN + (size_t)(blockIdx.x & 15) * CT;
    const float* xblk = x + row;                      // channel 0 of this ctile
    float*       yp0  = y + row + lane;               // this thread's channel

    // ---- cp.async tile copier: TILE_T x CT floats = 1024 float4
    // f = j*256 + tid : row = f>>3 (CT/4 = 8 float4 per row), col4 = f&7
    auto copy_tile = [&](int tile, int buf) {
        const float* src = xblk + (size_t)tile * TILE_T * C_LEN;
        uint32_t sdst = (uint32_t)__cvta_generic_to_shared(&sx[buf][0]);
        #pragma unroll
        for (int j = 0; j < 4; j++) {
            int f  = j * 256 + tid;
            int r  = f >> 3;
            int c4 = f & 7;
            cp_async16(sdst + (uint32_t)f * 16,
                       src + (size_t)r * C_LEN + c4 * 4);
        }
    };

    // ---- prologue: prefetch tiles 0 and 1
    copy_tile(0, 0); CP_COMMIT();
    copy_tile(1, 1); CP_COMMIT();
    if (tid < CT) sm_base[0][tid] = 0.0f;             // visible after barrier A(0)

    #pragma unroll 1
    for (int tile = 0; tile < NTILES; tile++) {
        const int p = tile & 1;

        CP_WAIT1();                 // this tile's copy complete (next may pend)
        __syncthreads();            // (A) buffer p visible to all warps

        // ---- read chunk from smem, compute chunk sum of u
        const float* sv = &sx[p][warp * LT * CT + lane];
        float v[LT];
        #pragma unroll
        for (int i = 0; i < LT; i++)
            v[i] = sv[i * CT];

        const bool has_t0 = (tile == 0) && (warp == 0);
        float ap_i = ap;
        float S = 0.0f;
        #pragma unroll
        for (int i = 0; i < LT; i++) {
            float wm = (has_t0 && i == 0) ? 1.0f : oma;
            S = fmaf(v[i] * wm, ap_i, S);
            ap_i *= a;
        }
        sm_part[warp][lane] = S;
        __syncthreads();            // (B) sm_part ready; all reads of sx[p] done

        // ---- refill buffer p with tile+2 (WAR-safe: after barrier B)
        if (tile + 2 < NTILES) copy_tile(tile + 2, p);
        CP_COMMIT();                // empty group at tail keeps counts aligned

        // ---- exclusive prefix over warps + running base
        float base = sm_base[p][lane];
        #pragma unroll
        for (int w = 0; w < WARPS - 1; w++)
            if (w < warp) base += sm_part[w][lane];
        if (warp == WARPS - 1)
            sm_base[p ^ 1][lane] = base + S;          // next tile's running total

        // ---- local scan; stream y out
        float* yp = yp0 + (size_t)(tile * TILE_T + warp * LT) * C_LEN;
        float Sc    = base;
        float ap_j  = ap;
        float iap_j = inv_ap;
        #pragma unroll
        for (int i = 0; i < LT; i++) {
            float wm = (has_t0 && i == 0) ? 1.0f : oma;
            Sc = fmaf(v[i] * wm, ap_j, Sc);
            __stcs(yp + (size_t)i * C_LEN, Sc * fminf(iap_j, INV_EPS));
            ap_j  *= a;
            iap_j *= inv_a;
        }

        // advance chunk-start powers by one tile (128 t)
        ap     *= aT;
        inv_ap *= iaT;
    }
}

extern "C" void kernel_launch(void* const* d_in, const int* in_sizes, int n_in,
                              void* d_out, int out_size)
{
    const float* x  = (const float*)d_in[0];
    const float* la = (const float*)d_in[1];
    float*       y  = (float*)d_out;

    int B = in_sizes[0] / (T_LEN * C_LEN);        // 32
    int blocks = B * (C_LEN / CT);                // 512
    ema_fused<<<blocks, 256>>>(x, la, y);
}

// round 14
// speedup vs baseline: 1.0782x; 1.0782x over previous
#include <cuda_runtime.h>
#include <cstdint>

// FastLearnableEMA — cp.async double-buffered pipeline, half-size CTAs.
//   a    = clip(sigmoid(logit_alpha), 1e-4, 1-1e-4)             [C]
//   u[t] = x[t]*w[t],  w[0]=1, w[t>0]=(1-a)*a^t
//   y[t] = cumsum_t(u) * min(a^-t, 1e8)     (== cumsum / max(a^t, 1e-8))
//
// Round-13 finding: 512 resident CTAs @4/SM leave a frozen 4-vs-3 CTA/SM
// imbalance (~14%) with no wave refill. Fix: 128-thread CTAs, CT=16,
// grid=1024 @8/SM -> still one wave, imbalance ~2%, more live warps.
// Each warp owns TWO 16-t chunks (lanes 0-15 / 16-31). x read once via
// cp.async.cg, y written once via .cs: 256 MB HBM total.

#define T_LEN   2048
#define C_LEN   512
#define CT      16                 // channels per block
#define WARPS   4
#define NCHUNK  (WARPS * 2)        // 8 chunks per tile
#define LT      16                 // t per chunk
#define TILE_T  (NCHUNK * LT)      // 128
#define NTILES  (T_LEN / TILE_T)   // 16
#define CLAMP_LO 1e-4f
#define CLAMP_HI (1.0f - 1e-4f)
#define INV_EPS  1e8f              // 1/eps

__device__ __forceinline__ void cp_async16(uint32_t saddr, const void* gptr) {
    asm volatile("cp.async.cg.shared.global [%0], [%1], 16;"
                 :: "r"(saddr), "l"(gptr));
}
#define CP_COMMIT() asm volatile("cp.async.commit_group;" ::: "memory")
#define CP_WAIT1()  asm volatile("cp.async.wait_group 1;"  ::: "memory")

__global__ void __launch_bounds__(128, 8) ema_fused(
    const float* __restrict__ x,
    const float* __restrict__ logit_alpha,
    float* __restrict__ y)
{
    const int tid  = threadIdx.x;
    const int warp = tid >> 5;
    const int lane = tid & 31;
    const int q    = lane >> 4;                       // chunk-half of warp
    const int cl   = lane & 15;                       // channel within ctile
    const int k    = (warp << 1) | q;                 // chunk id 0..7

    const int b    = blockIdx.x >> 5;                 // C/CT = 32 ctiles per b
    const int ct   = blockIdx.x & 31;
    const int c    = ct * CT + cl;

    __shared__ float sx[2][TILE_T * CT];              // 2 x 8 KB x staging
    __shared__ float sm_part[NCHUNK][CT];
    __shared__ float sm_base[2][CT];

    // per-channel constants
    float la  = logit_alpha[c];
    float a   = 1.0f / (1.0f + expf(-la));
    a = fminf(fmaxf(a, CLAMP_LO), CLAMP_HI);
    const float oma   = 1.0f - a;
    const float inv_a = 1.0f / a;
    const float lg2a  = log2f(a);

    // a^TILE_T, a^-TILE_T (tile stride 128 = 2^7) by repeated squaring
    float aT = a;
    #pragma unroll
    for (int i = 0; i < 7; i++) aT *= aT;             // a^128 (underflow->0 ok)
    float iaT = inv_a;
    #pragma unroll
    for (int i = 0; i < 7; i++) iaT *= iaT;           // a^-128 (inf ok, clamped)

    // chunk-start powers at t = k*LT (exact 1.0 for chunk 0)
    const float t0k   = (float)(k * LT);
    float ap     = (k == 0) ? 1.0f : exp2f(t0k * lg2a);
    float inv_ap = (k == 0) ? 1.0f : exp2f(-t0k * lg2a);

    const size_t row  = (size_t)b * T_LEN * C_LEN + (size_t)ct * CT;
    const float* xblk = x + row;                      // channel 0 of this ctile
    float*       yp0  = y + row + cl;                 // this thread's channel

    // ---- cp.async tile copier: TILE_T x CT floats = 512 float4
    // CT=16 -> 4 float4 per t-row: r = f>>2, c4 = f&3
    auto copy_tile = [&](int tile, int buf) {
        const float* src = xblk + (size_t)tile * TILE_T * C_LEN;
        uint32_t sdst = (uint32_t)__cvta_generic_to_shared(&sx[buf][0]);
        #pragma unroll
        for (int j = 0; j < 4; j++) {
            int f  = j * 128 + tid;
            int r  = f >> 2;
            int c4 = f & 3;
            cp_async16(sdst + (uint32_t)f * 16,
                       src + (size_t)r * C_LEN + c4 * 4);
        }
    };

    // ---- prologue: prefetch tiles 0 and 1
    copy_tile(0, 0); CP_COMMIT();
    copy_tile(1, 1); CP_COMMIT();
    if (tid < CT) sm_base[0][tid] = 0.0f;             // ordered by barrier A(0)

    #pragma unroll 1
    for (int tile = 0; tile < NTILES; tile++) {
        const int p = tile & 1;

        CP_WAIT1();                 // this tile's copy complete (next may pend)
        __syncthreads();            // (A) buffer p visible to all warps

        // ---- read chunk from smem, compute chunk sum of u
        const float* sv = &sx[p][k * LT * CT + cl];
        float v[LT];
        #pragma unroll
        for (int i = 0; i < LT; i++)
            v[i] = sv[i * CT];

        const bool has_t0 = (tile == 0) && (k == 0);
        float ap_i = ap;
        float S = 0.0f;
        #pragma unroll
        for (int i = 0; i < LT; i++) {
            float wm = (has_t0 && i == 0) ? 1.0f : oma;
            S = fmaf(v[i] * wm, ap_i, S);
            ap_i *= a;
        }
        sm_part[k][cl] = S;
        __syncthreads();            // (B) sm_part ready; all reads of sx[p] done

        // ---- refill buffer p with tile+2 (WAR-safe: after barrier B)
        if (tile + 2 < NTILES) copy_tile(tile + 2, p);
        CP_COMMIT();                // empty group at tail keeps counts aligned

        // ---- exclusive prefix over chunks + running base
        float base = sm_base[p][cl];
        #pragma unroll
        for (int j = 0; j < NCHUNK - 1; j++)
            if (j < k) base += sm_part[j][cl];
        if (k == NCHUNK - 1)
            sm_base[p ^ 1][cl] = base + S;            // next tile's running total

        // ---- local scan; stream y out
        float* yp = yp0 + (size_t)(tile * TILE_T + k * LT) * C_LEN;
        float Sc    = base;
        float ap_j  = ap;
        float iap_j = inv_ap;
        #pragma unroll
        for (int i = 0; i < LT; i++) {
            float wm = (has_t0 && i == 0) ? 1.0f : oma;
            Sc = fmaf(v[i] * wm, ap_j, Sc);
            __stcs(yp + (size_t)i * C_LEN, Sc * fminf(iap_j, INV_EPS));
            ap_j  *= a;
            iap_j *= inv_a;
        }

        // advance chunk-start powers by one tile (128 t)
        ap     *= aT;
        inv_ap *= iaT;
    }
}

extern "C" void kernel_launch(void* const* d_in, const int* in_sizes, int n_in,
                              void* d_out, int out_size)
{
    const float* x  = (const float*)d_in[0];
    const float* la = (const float*)d_in[1];
    float*       y  = (float*)d_out;

    int B = in_sizes[0] / (T_LEN * C_LEN);        // 32
    int blocks = B * (C_LEN / CT);                // 1024
    ema_fused<<<blocks, 128>>>(x, la, y);
}